// round 14
// baseline (speedup 1.0000x reference)
#include <cuda_runtime.h>
#include <cuda_bf16.h>

// (B,H,N,D,K2) = (4,8,4096,64,16); FFT length 2N=8192 real -> packed 4096-pt complex FFT.
#define THREADS 256
#define TFFT 512
// XOR bank swizzle on float4 indices.
#define SW(i) ((i) ^ (((i) >> 3) & 7))

// Packed time-domain filter a: g_pa[(h*32+dp)*4096 + tt]
__device__ float4 g_pa[256 * 4096];
// Filter spectrum, permuted layout: index (u<<9)+m holds data for spectrum slot p=8m+u.
// g_Af = X[f], g_Ag = X[4096-f], f = (u<<9)|revoct(m).
__device__ float4 g_Af[256 * 4096];
__device__ float4 g_Ag[256 * 4096];
// Transposed input/output: g_px[(bh*32+dp)*2048 + t] = (x0[2t],x0[2t+1],x1[2t],x1[2t+1])
__device__ float4 g_px[1024 * 2048];
__device__ float4 g_py[1024 * 2048];

// C8[u] = exp(-i pi u/8)
__constant__ float2 c_C8[8] = {
    { 1.000000000000000f,  0.000000000000000f}, { 0.923879532511287f, -0.382683432365090f},
    { 0.707106781186548f, -0.707106781186548f}, { 0.382683432365090f, -0.923879532511287f},
    { 0.000000000000000f, -1.000000000000000f}, {-0.382683432365090f, -0.923879532511287f},
    {-0.707106781186548f, -0.707106781186548f}, {-0.923879532511287f, -0.382683432365090f}};

__device__ __forceinline__ float2 cmul(float2 a, float2 b) {
    return make_float2(a.x * b.x - a.y * b.y, a.x * b.y + a.y * b.x);
}
__device__ __forceinline__ float4 f4add(float4 a, float4 b) {
    return make_float4(a.x + b.x, a.y + b.y, a.z + b.z, a.w + b.w);
}
__device__ __forceinline__ float4 f4sub(float4 a, float4 b) {
    return make_float4(a.x - b.x, a.y - b.y, a.z - b.z, a.w - b.w);
}
__device__ __forceinline__ float4 f4mulni(float4 v) { return make_float4(v.y, -v.x, v.w, -v.z); }
__device__ __forceinline__ float4 f4muli(float4 v)  { return make_float4(-v.y, v.x, -v.w, v.z); }
__device__ __forceinline__ float4 f4cmul(float4 v, float2 w) {
    return make_float4(v.x * w.x - v.y * w.y, v.x * w.y + v.y * w.x,
                       v.z * w.x - v.w * w.y, v.z * w.y + v.w * w.x);
}
// reverse 4 octal digits of a 12-bit value
__device__ __forceinline__ int rev8_12(int v) {
    return ((v & 7) << 9) | (((v >> 3) & 7) << 6) | (((v >> 6) & 7) << 3) | ((v >> 9) & 7);
}

// ---------------- radix-8 butterflies (two packed channels per float4) -----
__device__ __forceinline__ void dft8_fwd(float4* x) {
    const float C = 0.70710678118654752440f;
    float4 u0 = f4add(x[0], x[4]), u1 = f4add(x[1], x[5]);
    float4 u2 = f4add(x[2], x[6]), u3 = f4add(x[3], x[7]);
    float4 v0 = f4sub(x[0], x[4]), v1 = f4sub(x[1], x[5]);
    float4 v2 = f4sub(x[2], x[6]), v3 = f4sub(x[3], x[7]);
    float4 a0 = f4add(u0, u2), a1 = f4sub(u0, u2);
    float4 a2 = f4add(u1, u3), a3 = f4mulni(f4sub(u1, u3));
    float4 z1 = make_float4(C * (v1.x + v1.y), C * (v1.y - v1.x),
                            C * (v1.z + v1.w), C * (v1.w - v1.z));      // * e^{-i pi/4}
    float4 z2 = f4mulni(v2);
    float4 z3 = make_float4(C * (v3.y - v3.x), -C * (v3.x + v3.y),
                            C * (v3.w - v3.z), -C * (v3.z + v3.w));     // * e^{-3i pi/4}
    float4 b0 = f4add(v0, z2), b1 = f4sub(v0, z2);
    float4 b2 = f4add(z1, z3), b3 = f4mulni(f4sub(z1, z3));
    x[0] = f4add(a0, a2); x[2] = f4add(a1, a3);
    x[4] = f4sub(a0, a2); x[6] = f4sub(a1, a3);
    x[1] = f4add(b0, b2); x[3] = f4add(b1, b3);
    x[5] = f4sub(b0, b2); x[7] = f4sub(b1, b3);
}
__device__ __forceinline__ void dft8_inv(float4* x) {
    const float C = 0.70710678118654752440f;
    float4 u0 = f4add(x[0], x[4]), u1 = f4add(x[1], x[5]);
    float4 u2 = f4add(x[2], x[6]), u3 = f4add(x[3], x[7]);
    float4 v0 = f4sub(x[0], x[4]), v1 = f4sub(x[1], x[5]);
    float4 v2 = f4sub(x[2], x[6]), v3 = f4sub(x[3], x[7]);
    float4 a0 = f4add(u0, u2), a1 = f4sub(u0, u2);
    float4 a2 = f4add(u1, u3), a3 = f4muli(f4sub(u1, u3));
    float4 z1 = make_float4(C * (v1.x - v1.y), C * (v1.x + v1.y),
                            C * (v1.z - v1.w), C * (v1.z + v1.w));      // * e^{+i pi/4}
    float4 z2 = f4muli(v2);
    float4 z3 = make_float4(-C * (v3.x + v3.y), C * (v3.x - v3.y),
                            -C * (v3.z + v3.w), C * (v3.z - v3.w));     // * e^{+3i pi/4}
    float4 b0 = f4add(v0, z2), b1 = f4sub(v0, z2);
    float4 b2 = f4add(z1, z3), b3 = f4muli(f4sub(z1, z3));
    x[0] = f4add(a0, a2); x[2] = f4add(a1, a3);
    x[4] = f4sub(a0, a2); x[6] = f4sub(a1, a3);
    x[1] = f4add(b0, b2); x[3] = f4add(b1, b3);
    x[5] = f4sub(b0, b2); x[7] = f4sub(b1, b3);
}

// twiddle chains (apply to x[1..7]); fwd uses negative angle, inv positive.
__device__ __forceinline__ void tw_fwd(float4* x, float ang) {
    float sn, cs; __sincosf(ang, &sn, &cs);
    float2 t1 = make_float2(cs, sn);
    float2 t2 = cmul(t1, t1), t3 = cmul(t2, t1), t4 = cmul(t2, t2);
    float2 t5 = cmul(t4, t1), t6 = cmul(t4, t2), t7 = cmul(t4, t3);
    x[1] = f4cmul(x[1], t1); x[2] = f4cmul(x[2], t2); x[3] = f4cmul(x[3], t3);
    x[4] = f4cmul(x[4], t4); x[5] = f4cmul(x[5], t5);
    x[6] = f4cmul(x[6], t6); x[7] = f4cmul(x[7], t7);
}

// middle smem rounds (512 threads: one butterfly each). lq in {6,3}.
__device__ __forceinline__ void round8_fwd(float4* s, int m, int lq) {
    int q = 1 << lq;
    int j = m & (q - 1);
    int base = ((m >> lq) << (lq + 3)) | j;
    float4 x[8];
#pragma unroll
    for (int k = 0; k < 8; ++k) x[k] = s[SW(base + k * q)];
    dft8_fwd(x);
    tw_fwd(x, -6.28318530717958647692f * (float)j / (float)(q << 3));
#pragma unroll
    for (int k = 0; k < 8; ++k) s[SW(base + k * q)] = x[k];
    __syncthreads();
}
__device__ __forceinline__ void round8_inv(float4* s, int m, int lq) {
    int q = 1 << lq;
    int j = m & (q - 1);
    int base = ((m >> lq) << (lq + 3)) | j;
    float4 x[8];
#pragma unroll
    for (int k = 0; k < 8; ++k) x[k] = s[SW(base + k * q)];
    tw_fwd(x, 6.28318530717958647692f * (float)j / (float)(q << 3));
    dft8_inv(x);
#pragma unroll
    for (int k = 0; k < 8; ++k) s[SW(base + k * q)] = x[k];
    __syncthreads();
}

// Per-element frequency multiply (proven in R8): returns Z'[f], both channels.
__device__ __forceinline__ float4 mid_zf(float4 Zf, float4 Zg, float4 Af, float4 Ag, float2 W) {
    const float sc = 0.5f * (1.0f / 4096.0f);
    float4 r;
    {   // channel 0 (.xy)
        float2 E  = make_float2(0.5f * (Zf.x + Zg.x), 0.5f * (Zf.y - Zg.y));
        float2 O  = make_float2(0.5f * (Zf.y + Zg.y), -0.5f * (Zf.x - Zg.x));
        float2 WO = cmul(W, O);
        float2 Xf = make_float2(E.x + WO.x, E.y + WO.y);          // X[f]
        float2 Xg = make_float2(E.x - WO.x, -(E.y - WO.y));       // X[4096-f]
        float2 Pf = cmul(Xf, make_float2(Af.x, Af.y));
        float2 Pg = cmul(Xg, make_float2(Ag.x, Ag.y));
        float2 S  = make_float2(Pf.x + Pg.x, Pf.y - Pg.y);
        float2 D  = make_float2(Pf.x - Pg.x, Pf.y + Pg.y);
        float2 T  = cmul(make_float2(W.y, W.x), D);               // i*conj(W)*D
        r.x = sc * (S.x + T.x); r.y = sc * (S.y + T.y);
    }
    {   // channel 1 (.zw)
        float2 E  = make_float2(0.5f * (Zf.z + Zg.z), 0.5f * (Zf.w - Zg.w));
        float2 O  = make_float2(0.5f * (Zf.w + Zg.w), -0.5f * (Zf.z - Zg.z));
        float2 WO = cmul(W, O);
        float2 Xf = make_float2(E.x + WO.x, E.y + WO.y);
        float2 Xg = make_float2(E.x - WO.x, -(E.y - WO.y));
        float2 Pf = cmul(Xf, make_float2(Af.z, Af.w));
        float2 Pg = cmul(Xg, make_float2(Ag.z, Ag.w));
        float2 S  = make_float2(Pf.x + Pg.x, Pf.y - Pg.y);
        float2 D  = make_float2(Pf.x - Pg.x, Pf.y + Pg.y);
        float2 T  = cmul(make_float2(W.y, W.x), D);
        r.z = sc * (S.x + T.x); r.w = sc * (S.y + T.y);
    }
    return r;
}

// ---------------------------------------------------------------------------
// k_in: transpose x[bh][time][d] -> g_px. Scalar smem (odd row stride). grid (64,32).
// ---------------------------------------------------------------------------
__global__ void __launch_bounds__(THREADS)
k_in(const float* __restrict__ x) {
    __shared__ float sT[64 * 65];          // sT[d][time], row stride 65
    int tid = threadIdx.x;
    int bh = blockIdx.y;
    int T0 = blockIdx.x * 64;
    const float4* x4 = (const float4*)(x + (size_t)bh * 4096 * 64);
    int rowb = tid >> 4, c = tid & 15;
#pragma unroll
    for (int r4 = 0; r4 < 4; ++r4) {
        int tl = r4 * 16 + rowb;
        float4 v = x4[(size_t)(T0 + tl) * 16 + c];
        sT[(4 * c + 0) * 65 + tl] = v.x;
        sT[(4 * c + 1) * 65 + tl] = v.y;
        sT[(4 * c + 2) * 65 + tl] = v.z;
        sT[(4 * c + 3) * 65 + tl] = v.w;
    }
    __syncthreads();
    int w = tid >> 5, l = tid & 31;
    int tglob = blockIdx.x * 32 + l;
#pragma unroll
    for (int i = 0; i < 4; ++i) {
        int dp = w * 4 + i;
        int d0 = 2 * dp;
        float a0 = sT[d0 * 65 + 2 * l];
        float a1 = sT[d0 * 65 + 2 * l + 1];
        float b0 = sT[(d0 + 1) * 65 + 2 * l];
        float b1 = sT[(d0 + 1) * 65 + 2 * l + 1];
        g_px[(size_t)(bh * 32 + dp) * 2048 + tglob] = make_float4(a0, a1, b0, b1);
    }
}

// ---------------------------------------------------------------------------
// k_outT: untranspose g_py -> out. grid (64,32). Scalar smem.
// ---------------------------------------------------------------------------
__global__ void __launch_bounds__(THREADS)
k_outT(float* __restrict__ out) {
    __shared__ float sT[64 * 65];
    int tid = threadIdx.x;
    int bh = blockIdx.y;
    int w = tid >> 5, l = tid & 31;
    int tglob = blockIdx.x * 32 + l;
#pragma unroll
    for (int i = 0; i < 4; ++i) {
        int dp = w * 4 + i;
        int d0 = 2 * dp;
        float4 v = g_py[(size_t)(bh * 32 + dp) * 2048 + tglob];
        sT[d0 * 65 + 2 * l]           = v.x;
        sT[d0 * 65 + 2 * l + 1]       = v.y;
        sT[(d0 + 1) * 65 + 2 * l]     = v.z;
        sT[(d0 + 1) * 65 + 2 * l + 1] = v.w;
    }
    __syncthreads();
    int T0 = blockIdx.x * 64;
    float4* o4 = (float4*)(out + (size_t)bh * 4096 * 64);
    int rowb = tid >> 4, c = tid & 15;
#pragma unroll
    for (int r4 = 0; r4 < 4; ++r4) {
        int tl = r4 * 16 + rowb;
        float4 v = make_float4(sT[(4 * c + 0) * 65 + tl], sT[(4 * c + 1) * 65 + tl],
                               sT[(4 * c + 2) * 65 + tl], sT[(4 * c + 3) * 65 + tl]);
        o4[(size_t)(T0 + tl) * 16 + c] = v;
    }
}

// ---------------------------------------------------------------------------
// K0a: basis combine. coef transposed to scoefT[d*20+k] for aligned float4 reads.
// grid (16, 8, 2), 256 thr: 16 dp per block.
// ---------------------------------------------------------------------------
__global__ void __launch_bounds__(THREADS)
k_basis(const float* __restrict__ decay, const float* __restrict__ cosv,
        const float* __restrict__ coef) {
    __shared__ __align__(16) float scoefT[64 * 20];
    int tid = threadIdx.x;
    int h = blockIdx.y;
    int tt = blockIdx.x * THREADS + tid;
    int dp0 = blockIdx.z * 16;
    for (int i = tid; i < 1024; i += THREADS) {
        int k = i >> 6, d = i & 63;
        scoefT[d * 20 + k] = coef[h * 1024 + i];
    }
    __syncthreads();
    int t0 = 2 * tt, t1 = 2 * tt + 1;
    const float4* cos4 = (const float4*)cosv;
    float4 r0[4], r1[4];
#pragma unroll
    for (int q = 0; q < 4; ++q) { r0[q] = cos4[t0 * 4 + q]; r1[q] = cos4[t1 * 4 + q]; }
    float de0 = decay[t0], de1 = decay[t1];
#pragma unroll
    for (int dpi = 0; dpi < 16; ++dpi) {
        int dp = dp0 + dpi, d0 = dp * 2;
        const float4* c0p = (const float4*)&scoefT[d0 * 20];        // 80B-aligned
        const float4* c1p = (const float4*)&scoefT[(d0 + 1) * 20];
        float a00 = 0.f, a10 = 0.f, a01 = 0.f, a11 = 0.f;
#pragma unroll
        for (int kq = 0; kq < 4; ++kq) {
            float4 w = c0p[kq], v = c1p[kq];
            float4 c0 = r0[kq], c1 = r1[kq];
            a00 += w.x * c0.x + w.y * c0.y + w.z * c0.z + w.w * c0.w;
            a10 += w.x * c1.x + w.y * c1.y + w.z * c1.z + w.w * c1.w;
            a01 += v.x * c0.x + v.y * c0.y + v.z * c0.z + v.w * c0.w;
            a11 += v.x * c1.x + v.y * c1.y + v.z * c1.z + v.w * c1.w;
        }
        g_pa[(size_t)(h * 32 + dp) * 4096 + tt] =
            make_float4(a00 * de0, a10 * de1, a01 * de0, a11 * de1);
    }
}

// ---------------------------------------------------------------------------
// K0b: filter FFT, fused first round + fused epilogue. grid (32,8), 512 thr.
// ---------------------------------------------------------------------------
__global__ void __launch_bounds__(TFFT)
k_fft_filter() {
    extern __shared__ float4 s[];
    int m = threadIdx.x;
    int dp = blockIdx.x, h = blockIdx.y;
    size_t off = (size_t)(h * 32 + dp) * 4096;
    float4 z[8];
    // fwd q=512 fused with gmem load
#pragma unroll
    for (int k = 0; k < 8; ++k) z[k] = g_pa[off + m + (k << 9)];
    dft8_fwd(z);
    tw_fwd(z, -1.5339807878856412e-3f * (float)m);     // -2pi/4096 * j
#pragma unroll
    for (int k = 0; k < 8; ++k) s[SW(m + (k << 9))] = z[k];
    __syncthreads();
    round8_fwd(s, m, 6);
    round8_fwd(s, m, 3);
    // fwd q=1 in regs; store for partners
    int b0 = m << 3;
#pragma unroll
    for (int k = 0; k < 8; ++k) z[k] = s[SW(b0 + k)];
    dft8_fwd(z);
#pragma unroll
    for (int k = 0; k < 8; ++k) s[SW(b0 + k)] = z[k];
    __syncthreads();
    // epilogue: own Zf in regs, partner from smem; emit Af/Ag in permuted layout
    int R = ((m & 7) << 6) | (m & 56) | (m >> 6);
    float sn, cs;
    __sincosf(-7.6699039394282061e-4f * (float)R, &sn, &cs);   // -pi/4096
    float2 Wg = make_float2(cs, sn);
#pragma unroll
    for (int u = 0; u < 8; ++u) {
        int f = (u << 9) | R;
        int g = (4096 - f) & 4095;
        int pq = rev8_12(g);
        float4 Zg = s[SW(pq)];
        float4 Zf = z[u];
        float2 W = cmul(Wg, c_C8[u]);
        float2 E0  = make_float2(0.5f * (Zf.x + Zg.x), 0.5f * (Zf.y - Zg.y));
        float2 O0  = make_float2(0.5f * (Zf.y + Zg.y), -0.5f * (Zf.x - Zg.x));
        float2 WO0 = cmul(W, O0);
        float2 E1  = make_float2(0.5f * (Zf.z + Zg.z), 0.5f * (Zf.w - Zg.w));
        float2 O1  = make_float2(0.5f * (Zf.w + Zg.w), -0.5f * (Zf.z - Zg.z));
        float2 WO1 = cmul(W, O1);
        g_Af[off + (u << 9) + m] =
            make_float4(E0.x + WO0.x, E0.y + WO0.y, E1.x + WO1.x, E1.y + WO1.y);
        g_Ag[off + (u << 9) + m] =
            make_float4(E0.x - WO0.x, -(E0.y - WO0.y), E1.x - WO1.x, -(E1.y - WO1.y));
    }
}

// ---------------------------------------------------------------------------
// K1: fused conv. grid (32 dp, 32 bh), 512 thr, 64KB smem.
// pack->fwd(q512) fused; fwd(q1)+mid+inv(q1) in regs; inv(q512)->store fused.
// ---------------------------------------------------------------------------
__global__ void __launch_bounds__(TFFT)
k_conv() {
    extern __shared__ float4 s[];
    int m = threadIdx.x;
    int dp = blockIdx.x, bh = blockIdx.y, h = bh & 7;

    const float4* xp = g_px + (size_t)(bh * 32 + dp) * 2048;
    float4 z[8];
#pragma unroll
    for (int k = 0; k < 4; ++k) z[k] = xp[m + (k << 9)];
#pragma unroll
    for (int k = 4; k < 8; ++k) z[k] = make_float4(0.f, 0.f, 0.f, 0.f);
    dft8_fwd(z);
    tw_fwd(z, -1.5339807878856412e-3f * (float)m);     // -2pi/4096 * j
#pragma unroll
    for (int k = 0; k < 8; ++k) s[SW(m + (k << 9))] = z[k];
    __syncthreads();
    round8_fwd(s, m, 6);
    round8_fwd(s, m, 3);

    // fwd q=1 in regs, store for partners
    int b0 = m << 3;
#pragma unroll
    for (int k = 0; k < 8; ++k) z[k] = s[SW(b0 + k)];
    dft8_fwd(z);
#pragma unroll
    for (int k = 0; k < 8; ++k) s[SW(b0 + k)] = z[k];
    __syncthreads();

    // mid in regs: own Zf = z[u], partner from smem, A from gmem (coalesced)
    size_t off = (size_t)(h * 32 + dp) * 4096;
    int R = ((m & 7) << 6) | (m & 56) | (m >> 6);
    float sn, cs;
    __sincosf(-7.6699039394282061e-4f * (float)R, &sn, &cs);   // -pi/4096
    float2 Wg = make_float2(cs, sn);
#pragma unroll
    for (int u = 0; u < 8; ++u) {
        int f = (u << 9) | R;
        int g = (4096 - f) & 4095;
        int pq = rev8_12(g);
        float4 Zg = s[SW(pq)];
        float4 Af = g_Af[off + (u << 9) + m];
        float4 Ag = g_Ag[off + (u << 9) + m];
        float2 W = cmul(Wg, c_C8[u]);
        z[u] = mid_zf(z[u], Zg, Af, Ag, W);
    }
    __syncthreads();       // all partner reads complete before overwrite

    // inv q=1 in regs
    dft8_inv(z);
#pragma unroll
    for (int k = 0; k < 8; ++k) s[SW(b0 + k)] = z[k];
    __syncthreads();
    round8_inv(s, m, 3);
    round8_inv(s, m, 6);

    // inv q=512 fused with output store (keep first half: k<4 <=> t<2048)
#pragma unroll
    for (int k = 0; k < 8; ++k) z[k] = s[SW(m + (k << 9))];
    tw_fwd(z, 1.5339807878856412e-3f * (float)m);      // +2pi/4096 * j (conj)
    dft8_inv(z);
    float4* yp = g_py + (size_t)(bh * 32 + dp) * 2048;
#pragma unroll
    for (int k = 0; k < 4; ++k) yp[m + (k << 9)] = z[k];
}

extern "C" void kernel_launch(void* const* d_in, const int* in_sizes, int n_in,
                              void* d_out, int out_size) {
    const float* x     = (const float*)d_in[0];
    const float* decay = (const float*)d_in[1];
    const float* cosv  = (const float*)d_in[2];
    const float* coef  = (const float*)d_in[3];
    // d_in[4] = index (arange(N)) -- identity gather of first N samples.
    float* out = (float*)d_out;

    cudaFuncSetAttribute(k_fft_filter, cudaFuncAttributeMaxDynamicSharedMemorySize, 65536);
    cudaFuncSetAttribute(k_conv,       cudaFuncAttributeMaxDynamicSharedMemorySize, 65536);

    k_basis     <<<dim3(16, 8, 2), THREADS>>>(decay, cosv, coef);
    k_in        <<<dim3(64, 32),   THREADS>>>(x);
    k_fft_filter<<<dim3(32, 8),    TFFT, 65536>>>();
    k_conv      <<<dim3(32, 32),   TFFT, 65536>>>();
    k_outT      <<<dim3(64, 32),   THREADS>>>(out);
}

// round 15
// speedup vs baseline: 1.2767x; 1.2767x over previous
#include <cuda_runtime.h>
#include <cuda_bf16.h>

// (B,H,N,D,K2) = (4,8,4096,64,16); FFT length 2N=8192 real -> packed 4096-pt complex FFT.
#define THREADS 256
// XOR bank swizzle on float4 indices.
#define SW(i) ((i) ^ (((i) >> 3) & 7))

// Packed time-domain filter a: g_pa[(h*32+dp)*4096 + tt]
__device__ float4 g_pa[256 * 4096];
// Filter spectrum in digit-reversed order: g_Af[off+p] = A[rev8(p)], g_Ag[off+p] = A[4096-rev8(p)]
__device__ float4 g_Af[256 * 4096];
__device__ float4 g_Ag[256 * 4096];
// Transposed input/output: g_px[(bh*32+dp)*2048 + t] = (x0[2t],x0[2t+1],x1[2t],x1[2t+1])
__device__ float4 g_px[1024 * 2048];
__device__ float4 g_py[1024 * 2048];

__device__ __forceinline__ float2 cmul(float2 a, float2 b) {
    return make_float2(a.x * b.x - a.y * b.y, a.x * b.y + a.y * b.x);
}
__device__ __forceinline__ float4 f4add(float4 a, float4 b) {
    return make_float4(a.x + b.x, a.y + b.y, a.z + b.z, a.w + b.w);
}
__device__ __forceinline__ float4 f4sub(float4 a, float4 b) {
    return make_float4(a.x - b.x, a.y - b.y, a.z - b.z, a.w - b.w);
}
__device__ __forceinline__ float4 f4mulni(float4 v) { return make_float4(v.y, -v.x, v.w, -v.z); }
__device__ __forceinline__ float4 f4muli(float4 v)  { return make_float4(-v.y, v.x, -v.w, v.z); }
__device__ __forceinline__ float4 f4cmul(float4 v, float2 w) {
    return make_float4(v.x * w.x - v.y * w.y, v.x * w.y + v.y * w.x,
                       v.z * w.x - v.w * w.y, v.z * w.y + v.w * w.x);
}
// reverse 4 octal digits of a 12-bit value
__device__ __forceinline__ int rev8_12(int v) {
    return ((v & 7) << 9) | (((v >> 3) & 7) << 6) | (((v >> 6) & 7) << 3) | ((v >> 9) & 7);
}

// ---------------- radix-8 butterflies (two packed channels per float4) -----
__device__ __forceinline__ void dft8_fwd(float4* x) {
    const float C = 0.70710678118654752440f;
    float4 u0 = f4add(x[0], x[4]), u1 = f4add(x[1], x[5]);
    float4 u2 = f4add(x[2], x[6]), u3 = f4add(x[3], x[7]);
    float4 v0 = f4sub(x[0], x[4]), v1 = f4sub(x[1], x[5]);
    float4 v2 = f4sub(x[2], x[6]), v3 = f4sub(x[3], x[7]);
    float4 a0 = f4add(u0, u2), a1 = f4sub(u0, u2);
    float4 a2 = f4add(u1, u3), a3 = f4mulni(f4sub(u1, u3));
    float4 z1 = make_float4(C * (v1.x + v1.y), C * (v1.y - v1.x),
                            C * (v1.z + v1.w), C * (v1.w - v1.z));      // * e^{-i pi/4}
    float4 z2 = f4mulni(v2);
    float4 z3 = make_float4(C * (v3.y - v3.x), -C * (v3.x + v3.y),
                            C * (v3.w - v3.z), -C * (v3.z + v3.w));     // * e^{-3i pi/4}
    float4 b0 = f4add(v0, z2), b1 = f4sub(v0, z2);
    float4 b2 = f4add(z1, z3), b3 = f4mulni(f4sub(z1, z3));
    x[0] = f4add(a0, a2); x[2] = f4add(a1, a3);
    x[4] = f4sub(a0, a2); x[6] = f4sub(a1, a3);
    x[1] = f4add(b0, b2); x[3] = f4add(b1, b3);
    x[5] = f4sub(b0, b2); x[7] = f4sub(b1, b3);
}
__device__ __forceinline__ void dft8_inv(float4* x) {
    const float C = 0.70710678118654752440f;
    float4 u0 = f4add(x[0], x[4]), u1 = f4add(x[1], x[5]);
    float4 u2 = f4add(x[2], x[6]), u3 = f4add(x[3], x[7]);
    float4 v0 = f4sub(x[0], x[4]), v1 = f4sub(x[1], x[5]);
    float4 v2 = f4sub(x[2], x[6]), v3 = f4sub(x[3], x[7]);
    float4 a0 = f4add(u0, u2), a1 = f4sub(u0, u2);
    float4 a2 = f4add(u1, u3), a3 = f4muli(f4sub(u1, u3));
    float4 z1 = make_float4(C * (v1.x - v1.y), C * (v1.x + v1.y),
                            C * (v1.z - v1.w), C * (v1.z + v1.w));      // * e^{+i pi/4}
    float4 z2 = f4muli(v2);
    float4 z3 = make_float4(-C * (v3.x + v3.y), C * (v3.x - v3.y),
                            -C * (v3.z + v3.w), C * (v3.z - v3.w));     // * e^{+3i pi/4}
    float4 b0 = f4add(v0, z2), b1 = f4sub(v0, z2);
    float4 b2 = f4add(z1, z3), b3 = f4muli(f4sub(z1, z3));
    x[0] = f4add(a0, a2); x[2] = f4add(a1, a3);
    x[4] = f4sub(a0, a2); x[6] = f4sub(a1, a3);
    x[1] = f4add(b0, b2); x[3] = f4add(b1, b3);
    x[5] = f4sub(b0, b2); x[7] = f4sub(b1, b3);
}

// twiddle chain: multiply x[1..7] by w^k, w = e^{i*ang}
__device__ __forceinline__ void tw_apply(float4* x, float ang) {
    float sn, cs; __sincosf(ang, &sn, &cs);
    float2 t1 = make_float2(cs, sn);
    float2 t2 = cmul(t1, t1), t3 = cmul(t2, t1), t4 = cmul(t2, t2);
    float2 t5 = cmul(t4, t1), t6 = cmul(t4, t2), t7 = cmul(t4, t3);
    x[1] = f4cmul(x[1], t1); x[2] = f4cmul(x[2], t2); x[3] = f4cmul(x[3], t3);
    x[4] = f4cmul(x[4], t4); x[5] = f4cmul(x[5], t5);
    x[6] = f4cmul(x[6], t6); x[7] = f4cmul(x[7], t7);
}

// ---------------- remaining FFT stages (after fused first stage) -----------
// fwd stages q=64, 8, 1 (lq = 6, 3, 0); natural -> octal-digit-reversed.
__device__ void fft8_fwd_rest(float4* s, int tid) {
#pragma unroll
    for (int lq = 6; lq >= 0; lq -= 3) {
        const int q = 1 << lq;
#pragma unroll
        for (int it = 0; it < 2; ++it) {
            int m = tid + (it << 8);
            int j = m & (q - 1);
            int base = ((m >> lq) << (lq + 3)) | j;
            float4 x[8];
#pragma unroll
            for (int k = 0; k < 8; ++k) x[k] = s[SW(base + k * q)];
            dft8_fwd(x);
            if (lq > 0)
                tw_apply(x, -6.28318530717958647692f * (float)j / (float)(q << 3));
#pragma unroll
            for (int k = 0; k < 8; ++k) s[SW(base + k * q)] = x[k];
        }
        __syncthreads();
    }
}
// inverse stages q=1, 8, 64 (lq = 0, 3, 6).
__device__ void fft8_inv_rest(float4* s, int tid) {
#pragma unroll
    for (int lq = 0; lq <= 6; lq += 3) {
        const int q = 1 << lq;
#pragma unroll
        for (int it = 0; it < 2; ++it) {
            int m = tid + (it << 8);
            int j = m & (q - 1);
            int base = ((m >> lq) << (lq + 3)) | j;
            float4 x[8];
#pragma unroll
            for (int k = 0; k < 8; ++k) x[k] = s[SW(base + k * q)];
            if (lq > 0)
                tw_apply(x, 6.28318530717958647692f * (float)j / (float)(q << 3));
            dft8_inv(x);
#pragma unroll
            for (int k = 0; k < 8; ++k) s[SW(base + k * q)] = x[k];
        }
        __syncthreads();
    }
}

// Frequency-domain step (one channel): unpack packed-real pair, multiply,
// repack. Returns Z'[f] and Z'[4096-f], scaled by invN.
__device__ __forceinline__ void mid_pair(float2 Zf, float2 Zg, float2 Af, float2 Ag,
                                         float2 W, float invN,
                                         float2* zf_out, float2* zg_out) {
    float2 E  = make_float2(0.5f * (Zf.x + Zg.x), 0.5f * (Zf.y - Zg.y));
    float2 O  = make_float2(0.5f * (Zf.y + Zg.y), -0.5f * (Zf.x - Zg.x));
    float2 WO = cmul(W, O);
    float2 Xf  = make_float2(E.x + WO.x, E.y + WO.y);
    float2 Xgc = make_float2(E.x - WO.x, E.y - WO.y);      // conj(X[4096-f])
    float2 Pf = cmul(Xf, Af);
    float2 Pg = cmul(make_float2(Xgc.x, -Xgc.y), Ag);
    float2 S  = make_float2(Pf.x + Pg.x, Pf.y - Pg.y);
    float2 Dd = make_float2(Pf.x - Pg.x, Pf.y + Pg.y);
    float2 T1 = cmul(make_float2(W.y, W.x), Dd);
    *zf_out = make_float2(0.5f * invN * (S.x + T1.x), 0.5f * invN * (S.y + T1.y));
    float2 S2 = make_float2(Pg.x + Pf.x, Pg.y - Pf.y);
    float2 D2 = make_float2(Pg.x - Pf.x, Pg.y + Pf.y);
    float2 T2 = cmul(make_float2(W.y, -W.x), D2);
    *zg_out = make_float2(0.5f * invN * (S2.x + T2.x), 0.5f * invN * (S2.y + T2.y));
}

__device__ __forceinline__ void mid_at(float4* s, const float4* Afp, const float4* Agp,
                                       int p, int pq, bool writeg, float invN) {
    int f = rev8_12(p);
    float4 Zf = s[SW(p)];
    float4 Zg = s[SW(pq)];
    float4 Afv = Afp[p];
    float4 Agv = Agp[p];
    float ang = -3.14159265358979323846f * (float)f * (1.0f / 4096.0f);
    float sn, cs; __sincosf(ang, &sn, &cs);
    float2 W = make_float2(cs, sn);
    float2 zf0, zg0, zf1, zg1;
    mid_pair(make_float2(Zf.x, Zf.y), make_float2(Zg.x, Zg.y),
             make_float2(Afv.x, Afv.y), make_float2(Agv.x, Agv.y), W, invN, &zf0, &zg0);
    mid_pair(make_float2(Zf.z, Zf.w), make_float2(Zg.z, Zg.w),
             make_float2(Afv.z, Afv.w), make_float2(Agv.z, Agv.w), W, invN, &zf1, &zg1);
    s[SW(p)] = make_float4(zf0.x, zf0.y, zf1.x, zf1.y);
    if (writeg) s[SW(pq)] = make_float4(zg0.x, zg0.y, zg1.x, zg1.y);
}

// ---------------------------------------------------------------------------
// k_in: transpose x[bh][time][d] -> g_px. Scalar smem (odd row stride). grid (64,32).
// ---------------------------------------------------------------------------
__global__ void __launch_bounds__(THREADS)
k_in(const float* __restrict__ x) {
    __shared__ float sT[64 * 65];          // sT[d][time], row stride 65
    int tid = threadIdx.x;
    int bh = blockIdx.y;
    int T0 = blockIdx.x * 64;
    const float4* x4 = (const float4*)(x + (size_t)bh * 4096 * 64);
    int rowb = tid >> 4, c = tid & 15;
#pragma unroll
    for (int r4 = 0; r4 < 4; ++r4) {
        int tl = r4 * 16 + rowb;
        float4 v = x4[(size_t)(T0 + tl) * 16 + c];
        sT[(4 * c + 0) * 65 + tl] = v.x;
        sT[(4 * c + 1) * 65 + tl] = v.y;
        sT[(4 * c + 2) * 65 + tl] = v.z;
        sT[(4 * c + 3) * 65 + tl] = v.w;
    }
    __syncthreads();
    int w = tid >> 5, l = tid & 31;
    int tglob = blockIdx.x * 32 + l;
#pragma unroll
    for (int i = 0; i < 4; ++i) {
        int dp = w * 4 + i;
        int d0 = 2 * dp;
        float a0 = sT[d0 * 65 + 2 * l];
        float a1 = sT[d0 * 65 + 2 * l + 1];
        float b0 = sT[(d0 + 1) * 65 + 2 * l];
        float b1 = sT[(d0 + 1) * 65 + 2 * l + 1];
        g_px[(size_t)(bh * 32 + dp) * 2048 + tglob] = make_float4(a0, a1, b0, b1);
    }
}

// ---------------------------------------------------------------------------
// k_outT: untranspose g_py -> out. grid (64,32). Scalar smem.
// ---------------------------------------------------------------------------
__global__ void __launch_bounds__(THREADS)
k_outT(float* __restrict__ out) {
    __shared__ float sT[64 * 65];
    int tid = threadIdx.x;
    int bh = blockIdx.y;
    int w = tid >> 5, l = tid & 31;
    int tglob = blockIdx.x * 32 + l;
#pragma unroll
    for (int i = 0; i < 4; ++i) {
        int dp = w * 4 + i;
        int d0 = 2 * dp;
        float4 v = g_py[(size_t)(bh * 32 + dp) * 2048 + tglob];
        sT[d0 * 65 + 2 * l]           = v.x;
        sT[d0 * 65 + 2 * l + 1]       = v.y;
        sT[(d0 + 1) * 65 + 2 * l]     = v.z;
        sT[(d0 + 1) * 65 + 2 * l + 1] = v.w;
    }
    __syncthreads();
    int T0 = blockIdx.x * 64;
    float4* o4 = (float4*)(out + (size_t)bh * 4096 * 64);
    int rowb = tid >> 4, c = tid & 15;
#pragma unroll
    for (int r4 = 0; r4 < 4; ++r4) {
        int tl = r4 * 16 + rowb;
        float4 v = make_float4(sT[(4 * c + 0) * 65 + tl], sT[(4 * c + 1) * 65 + tl],
                               sT[(4 * c + 2) * 65 + tl], sT[(4 * c + 3) * 65 + tl]);
        o4[(size_t)(T0 + tl) * 16 + c] = v;
    }
}

// ---------------------------------------------------------------------------
// K0a: basis combine. cosv read once. grid=(16,8), 256 thr. (12.0us measured)
// ---------------------------------------------------------------------------
__global__ void __launch_bounds__(THREADS)
k_basis(const float* __restrict__ decay, const float* __restrict__ cosv,
        const float* __restrict__ coef) {
    __shared__ float scoef[16 * 64];
    int tid = threadIdx.x;
    int h = blockIdx.y;
    int tt = blockIdx.x * THREADS + tid;
    for (int i = tid; i < 1024; i += THREADS) scoef[i] = coef[h * 1024 + i];
    __syncthreads();
    int t0 = 2 * tt, t1 = 2 * tt + 1;
    const float4* cos4 = (const float4*)cosv;
    float4 r0[4], r1[4];
#pragma unroll
    for (int q = 0; q < 4; ++q) { r0[q] = cos4[t0 * 4 + q]; r1[q] = cos4[t1 * 4 + q]; }
    float de0 = decay[t0], de1 = decay[t1];
    for (int dp = 0; dp < 32; ++dp) {
        int d0 = dp * 2;
        float a00 = 0.f, a10 = 0.f, a01 = 0.f, a11 = 0.f;
#pragma unroll
        for (int kq = 0; kq < 4; ++kq) {
            float4 c0 = r0[kq], c1 = r1[kq];
            float w0 = scoef[(kq * 4 + 0) * 64 + d0], w1 = scoef[(kq * 4 + 1) * 64 + d0];
            float w2 = scoef[(kq * 4 + 2) * 64 + d0], w3 = scoef[(kq * 4 + 3) * 64 + d0];
            float v0 = scoef[(kq * 4 + 0) * 64 + d0 + 1], v1 = scoef[(kq * 4 + 1) * 64 + d0 + 1];
            float v2 = scoef[(kq * 4 + 2) * 64 + d0 + 1], v3 = scoef[(kq * 4 + 3) * 64 + d0 + 1];
            a00 += w0 * c0.x + w1 * c0.y + w2 * c0.z + w3 * c0.w;
            a10 += w0 * c1.x + w1 * c1.y + w2 * c1.z + w3 * c1.w;
            a01 += v0 * c0.x + v1 * c0.y + v2 * c0.z + v3 * c0.w;
            a11 += v0 * c1.x + v1 * c1.y + v2 * c1.z + v3 * c1.w;
        }
        g_pa[(size_t)(h * 32 + dp) * 4096 + tt] =
            make_float4(a00 * de0, a10 * de1, a01 * de0, a11 * de1);
    }
}

// ---------------------------------------------------------------------------
// K0b: filter FFT (fused load + stage q=512); emit Af/Ag digit-reversed. grid (32,8).
// ---------------------------------------------------------------------------
__global__ void __launch_bounds__(THREADS)
k_fft_filter() {
    extern __shared__ float4 s[];
    int tid = threadIdx.x;
    int dp = blockIdx.x, h = blockIdx.y;
    size_t off = (size_t)(h * 32 + dp) * 4096;

    // Fused: load g_pa -> stage q=512 butterfly -> smem
#pragma unroll
    for (int it = 0; it < 2; ++it) {
        int j = tid + (it << 8);
        float4 z[8];
#pragma unroll
        for (int k = 0; k < 8; ++k) z[k] = g_pa[off + j + (k << 9)];
        dft8_fwd(z);
        tw_apply(z, -1.5339807878856412e-3f * (float)j);     // -2pi/4096 * j
#pragma unroll
        for (int k = 0; k < 8; ++k) s[SW(j + (k << 9))] = z[k];
    }
    __syncthreads();
    fft8_fwd_rest(s, tid);

    float4* Afp = g_Af + off;
    float4* Agp = g_Ag + off;
    for (int i = 0; i < 16; ++i) {
        int p = tid + (i << 8);
        int f = rev8_12(p);
        int pg = rev8_12((4096 - f) & 4095);
        float4 Zf = s[SW(p)];
        float4 Zg = s[SW(pg)];
        float ang = -3.14159265358979323846f * (float)f * (1.0f / 4096.0f);
        float sn, cs; __sincosf(ang, &sn, &cs);
        float2 W = make_float2(cs, sn);
        float2 E0  = make_float2(0.5f * (Zf.x + Zg.x), 0.5f * (Zf.y - Zg.y));
        float2 O0  = make_float2(0.5f * (Zf.y + Zg.y), -0.5f * (Zf.x - Zg.x));
        float2 WO0 = cmul(W, O0);
        float2 E1  = make_float2(0.5f * (Zf.z + Zg.z), 0.5f * (Zf.w - Zg.w));
        float2 O1  = make_float2(0.5f * (Zf.w + Zg.w), -0.5f * (Zf.z - Zg.z));
        float2 WO1 = cmul(W, O1);
        Afp[p] = make_float4(E0.x + WO0.x, E0.y + WO0.y, E1.x + WO1.x, E1.y + WO1.y);
        Agp[p] = make_float4(E0.x - WO0.x, -(E0.y - WO0.y), E1.x - WO1.x, -(E1.y - WO1.y));
    }
}

// ---------------------------------------------------------------------------
// K1: per (b,h,d-pair). Fused: coalesced g_px load -> fwd q=512; middle rounds;
// region-paired mid; inverse rounds; inv q=512 -> coalesced g_py store.
// grid = (32 dp, 32 bh), 256 thr.
// ---------------------------------------------------------------------------
__global__ void __launch_bounds__(THREADS)
k_conv() {
    extern __shared__ float4 s[];
    int tid = threadIdx.x;
    int dp = blockIdx.x;
    int bh = blockIdx.y;
    int h  = bh & 7;

    // Fused fwd q=512 with coalesced pack load (k<4 data, k>=4 zero pad).
    const float4* xp = g_px + (size_t)(bh * 32 + dp) * 2048;
#pragma unroll
    for (int it = 0; it < 2; ++it) {
        int j = tid + (it << 8);
        float4 z[8];
#pragma unroll
        for (int k = 0; k < 4; ++k) z[k] = xp[j + (k << 9)];
#pragma unroll
        for (int k = 4; k < 8; ++k) z[k] = make_float4(0.f, 0.f, 0.f, 0.f);
        dft8_fwd(z);
        tw_apply(z, -1.5339807878856412e-3f * (float)j);     // -2pi/4096 * j
#pragma unroll
        for (int k = 0; k < 8; ++k) s[SW(j + (k << 9))] = z[k];
    }
    __syncthreads();
    fft8_fwd_rest(s, tid);

    size_t off = (size_t)(h * 32 + dp) * 4096;
    const float4* Afp = g_Af + off;
    const float4* Agp = g_Ag + off;
    const float invN = 1.0f / 4096.0f;
    // Pair-disjoint mid passes (regions proven disjoint; no sync needed between):
#pragma unroll
    for (int i = 0; i < 7; ++i) {        // [512,2304) with partners [2304,4096)
        int p = 512 + tid + (i << 8);
        int pq = ((8 - (p >> 9)) << 9) | (~p & 511);
        mid_at(s, Afp, Agp, p, pq, true, invN);
    }
    if (tid < 224) {          // [64,288) with partners [288,512)
        int p = 64 + tid;
        int pq = ((8 - (p >> 6)) << 6) | (~p & 63);
        mid_at(s, Afp, Agp, p, pq, true, invN);
    }
    if (tid < 28) {           // [8,36) with partners [36,64)
        int p = 8 + tid;
        int pq = ((8 - (p >> 3)) << 3) | (~p & 7);
        mid_at(s, Afp, Agp, p, pq, true, invN);
    }
    if (tid < 5) {            // [0,5): p=0 and p=4 are self-paired
        int p = tid;
        bool selfp = (p == 0) | (p == 4);
        int pq = selfp ? p : (8 - p);
        mid_at(s, Afp, Agp, p, pq, !selfp, invN);
    }
    __syncthreads();
    fft8_inv_rest(s, tid);

    // Fused inv q=512 -> coalesced store of kept half (k<4 <=> t<2048).
    float4* yp = g_py + (size_t)(bh * 32 + dp) * 2048;
#pragma unroll
    for (int it = 0; it < 2; ++it) {
        int j = tid + (it << 8);
        float4 z[8];
#pragma unroll
        for (int k = 0; k < 8; ++k) z[k] = s[SW(j + (k << 9))];
        tw_apply(z, 1.5339807878856412e-3f * (float)j);      // +2pi/4096 * j (conj)
        dft8_inv(z);
#pragma unroll
        for (int k = 0; k < 4; ++k) yp[j + (k << 9)] = z[k];
    }
}

extern "C" void kernel_launch(void* const* d_in, const int* in_sizes, int n_in,
                              void* d_out, int out_size) {
    const float* x     = (const float*)d_in[0];
    const float* decay = (const float*)d_in[1];
    const float* cosv  = (const float*)d_in[2];
    const float* coef  = (const float*)d_in[3];
    // d_in[4] = index (arange(N)) -- identity gather of first N samples.
    float* out = (float*)d_out;

    cudaFuncSetAttribute(k_fft_filter, cudaFuncAttributeMaxDynamicSharedMemorySize, 65536);
    cudaFuncSetAttribute(k_conv,       cudaFuncAttributeMaxDynamicSharedMemorySize, 65536);

    k_basis     <<<dim3(16, 8),  THREADS>>>(decay, cosv, coef);
    k_in        <<<dim3(64, 32), THREADS>>>(x);
    k_fft_filter<<<dim3(32, 8),  THREADS, 65536>>>();
    k_conv      <<<dim3(32, 32), THREADS, 65536>>>();
    k_outT      <<<dim3(64, 32), THREADS>>>(out);
}